// round 1
// baseline (speedup 1.0000x reference)
#include <cuda_runtime.h>
#include <math.h>

// Problem constants
#define Bc   4
#define L1c  1024
#define L2c  512
#define Lc   1536      // L1 + L2
#define DPGc 2304
#define DEXc 1024
#define Hc   8
#define HKVc 4
#define DHc  256
#define SCALEc 0.0625f // 256^-0.5

// Scratch (device globals: allocation-free per harness rules)
__device__ float g_q[(size_t)Bc * Lc * Hc * DHc];       // [B, L, H, DH]
__device__ float g_k[(size_t)Bc * Lc * HKVc * DHc];     // [B, L, HKV, DH]
__device__ float g_v[(size_t)Bc * Lc * HKVc * DHc];     // [B, L, HKV, DH]
__device__ float g_att[(size_t)Bc * Lc * Hc * DHc];     // [B, L, H*DH]
__device__ float g_scores[(size_t)Bc * Hc * Lc * Lc];   // [B, H, L, L]

// ---------------------------------------------------------------------------
// Generic batched GEMM: C = alpha * A @ op(B) + D
//   A: [M, K] row-major, lda
//   TB=true : B is [N, K] row-major (dot over K)   -> C[m,n] = sum_k A[m,k]*B[n,k]
//   TB=false: B is [K, N] row-major                -> C[m,n] = sum_k A[m,k]*B[k,n]
// Batch z: outer zo = z/div, inner zi = z%div.
//   A += zo*sAo + zi*sAi ; B += zo*sBo + (zi/rep)*sBi ; C += zo*sCo + zi*sCi
//   D (optional bias/mask, [M,N] ld=ldd) += zo*sDo
// Tiles: BM=BN=64, BK=16; 256 threads; 4x4 per thread.
// Assumes K % 16 == 0 and all float4 accesses aligned (true for all call sites).
// ---------------------------------------------------------------------------
#define GBM 64
#define GBN 64
#define GBK 16

template <bool TB>
__global__ void gemm_kernel(const float* __restrict__ A, const float* __restrict__ B,
                            float* __restrict__ C, const float* __restrict__ D,
                            int M, int N, int K,
                            int lda, int ldb, int ldc, int ldd,
                            long sAo, long sAi, long sBo, long sBi,
                            long sCo, long sCi, long sDo,
                            int div, int rep, float alpha)
{
    int z  = blockIdx.z;
    int zo = z / div;
    int zi = z % div;
    A += (long)zo * sAo + (long)zi * sAi;
    B += (long)zo * sBo + (long)(zi / rep) * sBi;
    C += (long)zo * sCo + (long)zi * sCi;
    if (D) D += (long)zo * sDo;

    int bm = blockIdx.y * GBM;
    int bn = blockIdx.x * GBN;

    __shared__ float As[GBK][GBM];
    __shared__ float Bs[GBK][GBN];

    int tid = threadIdx.x;
    int tr  = (tid / 16) * 4;   // 0..60
    int tc  = (tid % 16) * 4;   // 0..60

    float acc[4][4] = {};

    for (int k0 = 0; k0 < K; k0 += GBK) {
        // Load A tile (64x16): thread -> row m = tid/4, 4 consecutive k
        {
            int m  = tid >> 2;
            int kk = (tid & 3) << 2;
            float4 a = make_float4(0.f, 0.f, 0.f, 0.f);
            if (bm + m < M)
                a = *(const float4*)&A[(long)(bm + m) * lda + k0 + kk];
            As[kk + 0][m] = a.x; As[kk + 1][m] = a.y;
            As[kk + 2][m] = a.z; As[kk + 3][m] = a.w;
        }
        // Load B tile
        if (TB) {
            int n  = tid >> 2;
            int kk = (tid & 3) << 2;
            float4 b = make_float4(0.f, 0.f, 0.f, 0.f);
            if (bn + n < N)
                b = *(const float4*)&B[(long)(bn + n) * ldb + k0 + kk];
            Bs[kk + 0][n] = b.x; Bs[kk + 1][n] = b.y;
            Bs[kk + 2][n] = b.z; Bs[kk + 3][n] = b.w;
        } else {
            int k = tid >> 4;          // 0..15
            int n = (tid & 15) << 2;   // 0..60
            float4 b = make_float4(0.f, 0.f, 0.f, 0.f);
            if (bn + n < N)
                b = *(const float4*)&B[(long)(k0 + k) * ldb + bn + n];
            Bs[k][n + 0] = b.x; Bs[k][n + 1] = b.y;
            Bs[k][n + 2] = b.z; Bs[k][n + 3] = b.w;
        }
        __syncthreads();

#pragma unroll
        for (int k = 0; k < GBK; k++) {
            float4 av = *(const float4*)&As[k][tr];
            float4 bv = *(const float4*)&Bs[k][tc];
            float a[4] = {av.x, av.y, av.z, av.w};
            float b[4] = {bv.x, bv.y, bv.z, bv.w};
#pragma unroll
            for (int i = 0; i < 4; i++)
#pragma unroll
                for (int j = 0; j < 4; j++)
                    acc[i][j] += a[i] * b[j];
        }
        __syncthreads();
    }

#pragma unroll
    for (int i = 0; i < 4; i++) {
        int m = bm + tr + i;
        if (m >= M) break;
#pragma unroll
        for (int j = 0; j < 4; j++) {
            int n = bn + tc + j;
            if (n >= N) continue;
            float val = acc[i][j] * alpha;
            if (D) val += D[(long)m * ldd + n];
            C[(long)m * ldc + n] = val;
        }
    }
}

// ---------------------------------------------------------------------------
// RoPE (in place) on x: [B, L, nh, DH]; cos/sin: [B, L, 1, DH/2]
// ---------------------------------------------------------------------------
__global__ void rope_kernel(float* __restrict__ x,
                            const float* __restrict__ cosp,
                            const float* __restrict__ sinp,
                            int nh, long total_pairs)
{
    long idx = (long)blockIdx.x * blockDim.x + threadIdx.x;
    if (idx >= total_pairs) return;
    int  d  = (int)(idx & 127);          // DH/2 = 128
    long t  = idx >> 7;
    int  h  = (int)(t % nh);
    long bl = t / nh;                    // b*L + l
    float c = cosp[bl * 128 + d];
    float s = sinp[bl * 128 + d];
    float* base = x + (bl * nh + h) * (long)DHc;
    float x1 = base[d];
    float x2 = base[d + 128];
    base[d]       = x1 * c - x2 * s;
    base[d + 128] = x2 * c + x1 * s;
}

// ---------------------------------------------------------------------------
// Row softmax over scores: one block per row of length L
// ---------------------------------------------------------------------------
__global__ void softmax_kernel(float* __restrict__ S, int L)
{
    long  row = blockIdx.x;
    float* p  = S + row * (long)L;
    int   tid = threadIdx.x;
    __shared__ float red[256];

    float mx = -INFINITY;
    for (int i = tid; i < L; i += 256) mx = fmaxf(mx, p[i]);
    red[tid] = mx;
    __syncthreads();
    for (int s = 128; s > 0; s >>= 1) {
        if (tid < s) red[tid] = fmaxf(red[tid], red[tid + s]);
        __syncthreads();
    }
    mx = red[0];
    __syncthreads();

    float sum = 0.f;
    for (int i = tid; i < L; i += 256) {
        float e = __expf(p[i] - mx);
        p[i] = e;
        sum += e;
    }
    red[tid] = sum;
    __syncthreads();
    for (int s = 128; s > 0; s >>= 1) {
        if (tid < s) red[tid] += red[tid + s];
        __syncthreads();
    }
    float inv = 1.f / red[0];
    for (int i = tid; i < L; i += 256) p[i] *= inv;
}

// ---------------------------------------------------------------------------
// Host-side launch helpers
// ---------------------------------------------------------------------------
static inline void run_gemm(bool tb,
                            const float* A, const float* B, float* C, const float* D,
                            int M, int N, int K,
                            int lda, int ldb, int ldc, int ldd,
                            long sAo, long sAi, long sBo, long sBi,
                            long sCo, long sCi, long sDo,
                            int nbatch, int dv, int rep, float alpha)
{
    dim3 grid((N + GBN - 1) / GBN, (M + GBM - 1) / GBM, nbatch);
    if (tb)
        gemm_kernel<true><<<grid, 256>>>(A, B, C, D, M, N, K, lda, ldb, ldc, ldd,
                                         sAo, sAi, sBo, sBi, sCo, sCi, sDo, dv, rep, alpha);
    else
        gemm_kernel<false><<<grid, 256>>>(A, B, C, D, M, N, K, lda, ldb, ldc, ldd,
                                          sAo, sAi, sBo, sBi, sCo, sCi, sDo, dv, rep, alpha);
}

extern "C" void kernel_launch(void* const* d_in, const int* in_sizes, int n_in,
                              void* d_out, int out_size)
{
    const float* pg   = (const float*)d_in[0];
    const float* ex   = (const float*)d_in[1];
    const float* cosp = (const float*)d_in[2];
    const float* sinp = (const float*)d_in[3];
    const float* mask = (const float*)d_in[4];
    const float* Wq0  = (const float*)d_in[5];
    const float* Wk0  = (const float*)d_in[6];
    const float* Wv0  = (const float*)d_in[7];
    const float* Wo0  = (const float*)d_in[8];
    const float* Wq1  = (const float*)d_in[9];
    const float* Wk1  = (const float*)d_in[10];
    const float* Wv1  = (const float*)d_in[11];
    const float* Wo1  = (const float*)d_in[12];
    float* out = (float*)d_out;

    float *q, *k, *v, *att, *sc;
    cudaGetSymbolAddress((void**)&q,   g_q);
    cudaGetSymbolAddress((void**)&k,   g_k);
    cudaGetSymbolAddress((void**)&v,   g_v);
    cudaGetSymbolAddress((void**)&att, g_att);
    cudaGetSymbolAddress((void**)&sc,  g_scores);

    const int HD  = Hc * DHc;     // 2048
    const int KVD = HKVc * DHc;   // 1024

    // --- QKV projections (NT gemms), batched over B ---
    // pg stream (rows 0..L1-1 of the concatenated sequence)
    run_gemm(true, pg, Wq0, q, nullptr, L1c, HD, DPGc, DPGc, DPGc, HD, 0,
             (long)L1c * DPGc, 0, 0, 0, (long)Lc * HD, 0, 0, Bc, 1, 1, 1.0f);
    run_gemm(true, pg, Wk0, k, nullptr, L1c, KVD, DPGc, DPGc, DPGc, KVD, 0,
             (long)L1c * DPGc, 0, 0, 0, (long)Lc * KVD, 0, 0, Bc, 1, 1, 1.0f);
    run_gemm(true, pg, Wv0, v, nullptr, L1c, KVD, DPGc, DPGc, DPGc, KVD, 0,
             (long)L1c * DPGc, 0, 0, 0, (long)Lc * KVD, 0, 0, Bc, 1, 1, 1.0f);
    // ex stream (rows L1..L-1)
    run_gemm(true, ex, Wq1, q + (long)L1c * HD, nullptr, L2c, HD, DEXc, DEXc, DEXc, HD, 0,
             (long)L2c * DEXc, 0, 0, 0, (long)Lc * HD, 0, 0, Bc, 1, 1, 1.0f);
    run_gemm(true, ex, Wk1, k + (long)L1c * KVD, nullptr, L2c, KVD, DEXc, DEXc, DEXc, KVD, 0,
             (long)L2c * DEXc, 0, 0, 0, (long)Lc * KVD, 0, 0, Bc, 1, 1, 1.0f);
    run_gemm(true, ex, Wv1, v + (long)L1c * KVD, nullptr, L2c, KVD, DEXc, DEXc, DEXc, KVD, 0,
             (long)L2c * DEXc, 0, 0, 0, (long)Lc * KVD, 0, 0, Bc, 1, 1, 1.0f);

    // --- RoPE on q and k ---
    {
        long tp_q = (long)Bc * Lc * Hc * (DHc / 2);
        long tp_k = (long)Bc * Lc * HKVc * (DHc / 2);
        rope_kernel<<<(int)((tp_q + 255) / 256), 256>>>(q, cosp, sinp, Hc, tp_q);
        rope_kernel<<<(int)((tp_k + 255) / 256), 256>>>(k, cosp, sinp, HKVc, tp_k);
    }

    // --- scores = q @ k^T * SCALE + mask  (batched over B*H, GQA rep=2) ---
    run_gemm(true, q, k, sc, mask, Lc, Lc, DHc,
             HD, KVD, Lc, Lc,
             (long)Lc * HD, DHc,            // A: + b*L*H*DH + h*DH
             (long)Lc * KVD, DHc,           // B: + b*L*HKV*DH + (h/2)*DH
             (long)Hc * Lc * Lc, (long)Lc * Lc,  // C
             (long)Lc * Lc,                 // D (mask per batch b)
             Bc * Hc, Hc, 2, SCALEc);

    // --- softmax over last dim ---
    softmax_kernel<<<Bc * Hc * Lc, 256>>>(sc, Lc);

    // --- att = P @ V  (NN gemm, batched over B*H, rep=2) ---
    run_gemm(false, sc, v, att, nullptr, Lc, DHc, Lc,
             Lc, KVD, HD, 0,
             (long)Hc * Lc * Lc, (long)Lc * Lc,
             (long)Lc * KVD, DHc,
             (long)Lc * HD, DHc,
             0, Bc * Hc, Hc, 2, 1.0f);

    // --- output projections ---
    // out0 = att[:, :L1] @ Wo0^T  -> [B, L1, D_PG] at out[0]
    run_gemm(true, att, Wo0, out, nullptr, L1c, DPGc, HD,
             HD, HD, DPGc, 0,
             (long)Lc * HD, 0, 0, 0,
             (long)L1c * DPGc, 0, 0, Bc, 1, 1, 1.0f);
    // out1 = att[:, L1:] @ Wo1^T  -> [B, L2, D_EX] appended after out0
    run_gemm(true, att + (long)L1c * HD, Wo1, out + (long)Bc * L1c * DPGc, nullptr,
             L2c, DEXc, HD,
             HD, HD, DEXc, 0,
             (long)Lc * HD, 0, 0, 0,
             (long)L2c * DEXc, 0, 0, Bc, 1, 1, 1.0f);
}

// round 3
// speedup vs baseline: 3.5017x; 3.5017x over previous
#include <cuda_runtime.h>
#include <cuda_bf16.h>
#include <math.h>
#include <stdint.h>

// Problem constants
#define Bc   4
#define L1c  1024
#define L2c  512
#define Lc   1536
#define DPGc 2304
#define DEXc 1024
#define Hc   8
#define HKVc 4
#define DHc  256
#define SCALEc 0.0625f

// ---------------------------------------------------------------------------
// Scratch (device globals; allocation-free)
// ---------------------------------------------------------------------------
__device__ __align__(128) float g_q[(size_t)Bc * Lc * Hc * DHc];
__device__ __align__(128) float g_k[(size_t)Bc * Lc * HKVc * DHc];
__device__ __align__(128) float g_v[(size_t)Bc * Lc * HKVc * DHc];
__device__ __align__(128) float g_att[(size_t)Bc * Lc * Hc * DHc];
__device__ __align__(128) float g_scores[(size_t)Bc * Hc * Lc * Lc];

#define DECL_HL(name, count) \
    __device__ __align__(128) __nv_bfloat16 name##_h[count]; \
    __device__ __align__(128) __nv_bfloat16 name##_l[count];

DECL_HL(g_pg,  (size_t)Bc * L1c * DPGc)
DECL_HL(g_ex,  (size_t)Bc * L2c * DEXc)
DECL_HL(g_wq0, (size_t)Hc * DHc * DPGc)
DECL_HL(g_wk0, (size_t)HKVc * DHc * DPGc)
DECL_HL(g_wv0, (size_t)HKVc * DHc * DPGc)
DECL_HL(g_wo0, (size_t)DPGc * Hc * DHc)
DECL_HL(g_wq1, (size_t)Hc * DHc * DEXc)
DECL_HL(g_wk1, (size_t)HKVc * DHc * DEXc)
DECL_HL(g_wv1, (size_t)HKVc * DHc * DEXc)
DECL_HL(g_wo1, (size_t)DEXc * Hc * DHc)
DECL_HL(g_qb,  (size_t)Bc * Lc * Hc * DHc)
DECL_HL(g_kb,  (size_t)Bc * Lc * HKVc * DHc)
DECL_HL(g_vt,  (size_t)Bc * HKVc * DHc * Lc)     // transposed V: [B*HKV, DH, L]
DECL_HL(g_p,   (size_t)Bc * Hc * Lc * Lc)
DECL_HL(g_attb,(size_t)Bc * Lc * Hc * DHc)

// ---------------------------------------------------------------------------
// PTX helpers (compute_103-safe: cp.async, ldmatrix, mma.sync only)
// ---------------------------------------------------------------------------
__device__ __forceinline__ uint32_t smem_u32(const void* p) {
    uint32_t a;
    asm("{ .reg .u64 t; cvta.to.shared.u64 t, %1; cvt.u32.u64 %0, t; }" : "=r"(a) : "l"(p));
    return a;
}
#define CP_ASYNC16(dst, src) \
    asm volatile("cp.async.cg.shared.global [%0], [%1], 16;" :: "r"(dst), "l"(src) : "memory")
#define CP_COMMIT() asm volatile("cp.async.commit_group;" ::: "memory")

#define LDMX4(r0, r1, r2, r3, addr) \
    asm volatile("ldmatrix.sync.aligned.m8n8.x4.shared.b16 {%0,%1,%2,%3}, [%4];" \
                 : "=r"(r0), "=r"(r1), "=r"(r2), "=r"(r3) : "r"(addr))

#define MMA16816(c, a, b0, b1) \
    asm volatile("mma.sync.aligned.m16n8k16.row.col.f32.bf16.bf16.f32 " \
                 "{%0,%1,%2,%3}, {%4,%5,%6,%7}, {%8,%9}, {%0,%1,%2,%3};" \
                 : "+f"((c)[0]), "+f"((c)[1]), "+f"((c)[2]), "+f"((c)[3]) \
                 : "r"((a)[0]), "r"((a)[1]), "r"((a)[2]), "r"((a)[3]), \
                   "r"(b0), "r"(b1))

// ---------------------------------------------------------------------------
// bf16x2-split GEMM via mma.sync.  C[m,n] = alpha * sum_k A[m,k]*B[n,k] (+ D)
// Tiles 128x128x64, double-buffered cp.async, SW128 swizzle, 256 threads.
// 3 compensation passes: Ah*Bh + Ah*Bl + Al*Bh, fp32 accumulate.
// Requires: M,N % 128 == 0, K % 64 == 0 (true at every call site).
// ---------------------------------------------------------------------------
#define STAGE_BYTES 65536                    // 4 tiles x 16KB (Ah,Bh,Al,Bl)
#define SMEM_BYTES  (2 * STAGE_BYTES + 1024)

__global__ void __launch_bounds__(256, 1) gemm_mma(
    const __nv_bfloat16* __restrict__ Ahi, const __nv_bfloat16* __restrict__ Alo,
    const __nv_bfloat16* __restrict__ Bhi, const __nv_bfloat16* __restrict__ Blo,
    float* __restrict__ C, const float* __restrict__ D,
    int M, int N, int K, int lda, int ldb, int ldc, int ldd,
    long sAo, long sAi, long sBo, long sBi, long sCo, long sCi, long sDo,
    int div_, int rep, float alpha)
{
    extern __shared__ char smem_raw[];
    uint32_t sb0 = smem_u32(smem_raw);
    uint32_t sb  = (sb0 + 1023) & ~1023u;
    char* smem_al = smem_raw + (sb - sb0);

    int tid = threadIdx.x, wid = tid >> 5, lane = tid & 31;
    int wm = wid & 1, wn = wid >> 1;      // warp grid 2 (m) x 4 (n)

    int z = blockIdx.z, zo = z / div_, zi = z % div_;
    long aoff = (long)zo * sAo + (long)zi * sAi;
    long boff = (long)zo * sBo + (long)(zi / rep) * sBi;
    Ahi += aoff; Alo += aoff; Bhi += boff; Blo += boff;
    C += (long)zo * sCo + (long)zi * sCi;
    if (D) D += (long)zo * sDo;

    int bm = blockIdx.y * 128;
    int bn = blockIdx.x * 128;

    float acc[4][4][4] = {};              // [mi][ni][reg]

    const int KT = K >> 6;

    // ---- stage loader: 4 tiles (Ah,Bh,Al,Bl), 128 rows x 128B, SW128 ----
#define LOAD_STAGE(ktv)                                                        \
    do {                                                                       \
        uint32_t stb_ = sb + ((ktv) & 1) * STAGE_BYTES;                        \
        int k0_ = (ktv) << 6;                                                  \
        _Pragma("unroll")                                                      \
        for (int tile = 0; tile < 4; tile++) {                                 \
            const __nv_bfloat16* base =                                        \
                (tile == 0) ? Ahi : (tile == 1) ? Bhi : (tile == 2) ? Alo : Blo;\
            int ld = (tile & 1) ? ldb : lda;                                   \
            int rb = (tile & 1) ? bn : bm;                                     \
            _Pragma("unroll")                                                  \
            for (int j = 0; j < 4; j++) {                                      \
                int idx = j * 256 + tid;                                       \
                int row = idx >> 3, c = idx & 7;                               \
                const __nv_bfloat16* src = base + (long)(rb + row) * ld + k0_ + c * 8; \
                uint32_t doff = (uint32_t)(row * 128 + c * 16);                \
                doff ^= (doff >> 3) & 0x70;                                    \
                CP_ASYNC16(stb_ + tile * 16384 + doff, src);                   \
            }                                                                  \
        }                                                                      \
        CP_COMMIT();                                                           \
    } while (0)

    LOAD_STAGE(0);

    for (int kt = 0; kt < KT; kt++) {
        if (kt + 1 < KT) {
            LOAD_STAGE(kt + 1);
            asm volatile("cp.async.wait_group 1;" ::: "memory");
        } else {
            asm volatile("cp.async.wait_group 0;" ::: "memory");
        }
        __syncthreads();

        uint32_t stb = sb + (kt & 1) * STAGE_BYTES;

#pragma unroll
        for (int ks = 0; ks < 4; ks++) {
            uint32_t ah[4][4], al[4][4], bh[4][2], bl[4][2];

            // A fragments (hi & lo): lanes 0-15 -> rows 0-15 k-low chunk,
            // lanes 16-31 -> rows 0-15 k-high chunk
            int arow0 = wm * 64 + (lane & 15);
            int ac    = 2 * ks + (lane >> 4);
#pragma unroll
            for (int mi = 0; mi < 4; mi++) {
                int r = arow0 + mi * 16;
                uint32_t off = (uint32_t)(r * 128 + ((ac ^ (r & 7)) << 4));
                LDMX4(ah[mi][0], ah[mi][1], ah[mi][2], ah[mi][3], stb + off);
                LDMX4(al[mi][0], al[mi][1], al[mi][2], al[mi][3], stb + 32768 + off);
            }
            // B fragments (hi & lo): 2 x ldmatrix.x4 covers 4 n8 tiles
            int bn0 = wn * 32 + ((lane >> 4) << 3) + (lane & 7);
            int bcc = 2 * ks + ((lane >> 3) & 1);
#pragma unroll
            for (int nj = 0; nj < 2; nj++) {
                int r = bn0 + nj * 16;
                uint32_t off = (uint32_t)(r * 128 + ((bcc ^ (r & 7)) << 4));
                uint32_t t0, t1, t2, t3;
                LDMX4(t0, t1, t2, t3, stb + 16384 + off);
                bh[2 * nj][0] = t0; bh[2 * nj][1] = t1;
                bh[2 * nj + 1][0] = t2; bh[2 * nj + 1][1] = t3;
                LDMX4(t0, t1, t2, t3, stb + 49152 + off);
                bl[2 * nj][0] = t0; bl[2 * nj][1] = t1;
                bl[2 * nj + 1][0] = t2; bl[2 * nj + 1][1] = t3;
            }
            // 3 compensated passes
#pragma unroll
            for (int mi = 0; mi < 4; mi++)
#pragma unroll
                for (int ni = 0; ni < 4; ni++) {
                    MMA16816(acc[mi][ni], ah[mi], bh[ni][0], bh[ni][1]);
                    MMA16816(acc[mi][ni], ah[mi], bl[ni][0], bl[ni][1]);
                    MMA16816(acc[mi][ni], al[mi], bh[ni][0], bh[ni][1]);
                }
        }
        __syncthreads();
    }

    // ---- epilogue: regs -> SMEM (stride 132) -> coalesced GMEM ----
    float* Ct = (float*)smem_al;
    int tq = lane >> 2, tr2 = (lane & 3) * 2;
#pragma unroll
    for (int mi = 0; mi < 4; mi++)
#pragma unroll
        for (int ni = 0; ni < 4; ni++) {
            int r0 = wm * 64 + mi * 16 + tq;
            int cc = wn * 32 + ni * 8 + tr2;
            *(float2*)&Ct[r0 * 132 + cc] =
                make_float2(acc[mi][ni][0] * alpha, acc[mi][ni][1] * alpha);
            *(float2*)&Ct[(r0 + 8) * 132 + cc] =
                make_float2(acc[mi][ni][2] * alpha, acc[mi][ni][3] * alpha);
        }
    __syncthreads();

#pragma unroll
    for (int it = 0; it < 16; it++) {
        int r = it * 8 + wid;
        float4 v = *(float4*)&Ct[r * 132 + lane * 4];
        if (D) {
            const float* dp = &D[(long)(bm + r) * ldd + bn + lane * 4];
            v.x += dp[0]; v.y += dp[1]; v.z += dp[2]; v.w += dp[3];
        }
        *(float4*)&C[(long)(bm + r) * ldc + bn + lane * 4] = v;
    }
}

// ---------------------------------------------------------------------------
// fp32 -> bf16 hi/lo split (elementwise, vectorized)
// ---------------------------------------------------------------------------
__global__ void cvt_kernel(const float* __restrict__ x,
                           __nv_bfloat16* __restrict__ h, __nv_bfloat16* __restrict__ l,
                           long n4)
{
    long i = (long)blockIdx.x * 256 + threadIdx.x;
    if (i >= n4) return;
    float4 v = ((const float4*)x)[i];
    __nv_bfloat16 h0 = __float2bfloat16(v.x), h1 = __float2bfloat16(v.y);
    __nv_bfloat16 h2 = __float2bfloat16(v.z), h3 = __float2bfloat16(v.w);
    __nv_bfloat16 l0 = __float2bfloat16(v.x - __bfloat162float(h0));
    __nv_bfloat16 l1 = __float2bfloat16(v.y - __bfloat162float(h1));
    __nv_bfloat16 l2 = __float2bfloat16(v.z - __bfloat162float(h2));
    __nv_bfloat16 l3 = __float2bfloat16(v.w - __bfloat162float(h3));
    ((__nv_bfloat162*)h)[i * 2 + 0] = __nv_bfloat162(h0, h1);
    ((__nv_bfloat162*)h)[i * 2 + 1] = __nv_bfloat162(h2, h3);
    ((__nv_bfloat162*)l)[i * 2 + 0] = __nv_bfloat162(l0, l1);
    ((__nv_bfloat162*)l)[i * 2 + 1] = __nv_bfloat162(l2, l3);
}

// ---------------------------------------------------------------------------
// RoPE + split: reads fp32 x [B,L,nh,256], writes bf16 hi/lo
// ---------------------------------------------------------------------------
__global__ void rope_cvt_kernel(const float* __restrict__ x,
                                const float* __restrict__ cosp, const float* __restrict__ sinp,
                                __nv_bfloat16* __restrict__ h, __nv_bfloat16* __restrict__ l,
                                int nh, long total_pairs)
{
    long idx = (long)blockIdx.x * 256 + threadIdx.x;
    if (idx >= total_pairs) return;
    int  d  = (int)(idx & 127);
    long t  = idx >> 7;
    int  hh = (int)(t % nh);
    long bl = t / nh;
    float c = cosp[bl * 128 + d];
    float s = sinp[bl * 128 + d];
    long base = (bl * nh + hh) * (long)DHc;
    float x1 = x[base + d], x2 = x[base + d + 128];
    float o1 = x1 * c - x2 * s;
    float o2 = x2 * c + x1 * s;
    __nv_bfloat16 h1b = __float2bfloat16(o1), h2b = __float2bfloat16(o2);
    h[base + d]       = h1b;
    h[base + d + 128] = h2b;
    l[base + d]       = __float2bfloat16(o1 - __bfloat162float(h1b));
    l[base + d + 128] = __float2bfloat16(o2 - __bfloat162float(h2b));
}

// ---------------------------------------------------------------------------
// V transpose + split: v [B, L, HKV*DH] -> vt [B*HKV, DH, L]
// ---------------------------------------------------------------------------
__global__ void vtrans_cvt_kernel(const float* __restrict__ v,
                                  __nv_bfloat16* __restrict__ vh, __nv_bfloat16* __restrict__ vl)
{
    __shared__ float ts[32][33];
    int z = blockIdx.z;                 // b*HKV + h
    const float* src = v + (long)(z / HKVc) * Lc * (HKVc * DHc) + (z % HKVc) * DHc;
    __nv_bfloat16* dh = vh + (long)z * DHc * Lc;
    __nv_bfloat16* dl = vl + (long)z * DHc * Lc;
    int l0 = blockIdx.y * 32, d0 = blockIdx.x * 32;
    int tx = threadIdx.x, ty = threadIdx.y;
#pragma unroll
    for (int j = 0; j < 4; j++)
        ts[ty + j * 8][tx] = src[(long)(l0 + ty + j * 8) * (HKVc * DHc) + d0 + tx];
    __syncthreads();
#pragma unroll
    for (int j = 0; j < 4; j++) {
        int d = d0 + ty + j * 8;
        float val = ts[tx][ty + j * 8];
        __nv_bfloat16 hb = __float2bfloat16(val);
        dh[(long)d * Lc + l0 + tx] = hb;
        dl[(long)d * Lc + l0 + tx] = __float2bfloat16(val - __bfloat162float(hb));
    }
}

// ---------------------------------------------------------------------------
// Softmax + split: reads fp32 scores row, writes bf16 hi/lo P
// ---------------------------------------------------------------------------
__global__ void softmax_cvt_kernel(const float* __restrict__ S,
                                   __nv_bfloat16* __restrict__ ph, __nv_bfloat16* __restrict__ pl,
                                   int L)
{
    long row = blockIdx.x;
    const float* p = S + row * (long)L;
    int tid = threadIdx.x;
    __shared__ float red[256];

    float mx = -INFINITY;
    for (int i = tid; i < L; i += 256) mx = fmaxf(mx, p[i]);
    red[tid] = mx;
    __syncthreads();
    for (int s = 128; s > 0; s >>= 1) {
        if (tid < s) red[tid] = fmaxf(red[tid], red[tid + s]);
        __syncthreads();
    }
    mx = red[0];
    __syncthreads();

    float sum = 0.f;
    for (int i = tid; i < L; i += 256) sum += __expf(p[i] - mx);
    red[tid] = sum;
    __syncthreads();
    for (int s = 128; s > 0; s >>= 1) {
        if (tid < s) red[tid] += red[tid + s];
        __syncthreads();
    }
    float inv = 1.f / red[0];

    __nv_bfloat16* hrow = ph + row * (long)L;
    __nv_bfloat16* lrow = pl + row * (long)L;
    for (int i = tid; i < L; i += 256) {
        float e = __expf(p[i] - mx) * inv;
        __nv_bfloat16 hb = __float2bfloat16(e);
        hrow[i] = hb;
        lrow[i] = __float2bfloat16(e - __bfloat162float(hb));
    }
}

// ---------------------------------------------------------------------------
// Host side
// ---------------------------------------------------------------------------
static inline void run_cvt(const float* x, __nv_bfloat16* h, __nv_bfloat16* l, long n)
{
    long n4 = n >> 2;
    cvt_kernel<<<(int)((n4 + 255) / 256), 256>>>(x, h, l, n4);
}

static inline void run_gemm_tc(const __nv_bfloat16* Ah, const __nv_bfloat16* Al,
                               const __nv_bfloat16* Bh, const __nv_bfloat16* Bl,
                               float* C, const float* D,
                               int M, int N, int K, int lda, int ldb, int ldc, int ldd,
                               long sAo, long sAi, long sBo, long sBi,
                               long sCo, long sCi, long sDo,
                               int nb, int dv, int rep, float alpha)
{
    dim3 grid(N / 128, M / 128, nb);
    gemm_mma<<<grid, 256, SMEM_BYTES>>>(Ah, Al, Bh, Bl, C, D, M, N, K,
                                        lda, ldb, ldc, ldd,
                                        sAo, sAi, sBo, sBi, sCo, sCi, sDo,
                                        dv, rep, alpha);
}

extern "C" void kernel_launch(void* const* d_in, const int* in_sizes, int n_in,
                              void* d_out, int out_size)
{
    const float* pg   = (const float*)d_in[0];
    const float* ex   = (const float*)d_in[1];
    const float* cosp = (const float*)d_in[2];
    const float* sinp = (const float*)d_in[3];
    const float* mask = (const float*)d_in[4];
    const float* W[8] = { (const float*)d_in[5],  (const float*)d_in[6],
                          (const float*)d_in[7],  (const float*)d_in[8],
                          (const float*)d_in[9],  (const float*)d_in[10],
                          (const float*)d_in[11], (const float*)d_in[12] };
    float* out = (float*)d_out;

    cudaFuncSetAttribute(gemm_mma, cudaFuncAttributeMaxDynamicSharedMemorySize, SMEM_BYTES);

    float *q, *k, *v, *att, *sc;
    cudaGetSymbolAddress((void**)&q,   g_q);
    cudaGetSymbolAddress((void**)&k,   g_k);
    cudaGetSymbolAddress((void**)&v,   g_v);
    cudaGetSymbolAddress((void**)&att, g_att);
    cudaGetSymbolAddress((void**)&sc,  g_scores);

#define GETHL(sym, hp, lp) \
    __nv_bfloat16 *hp, *lp; \
    cudaGetSymbolAddress((void**)&hp, sym##_h); \
    cudaGetSymbolAddress((void**)&lp, sym##_l);

    GETHL(g_pg,  pgh,  pgl)   GETHL(g_ex,  exh,  exl)
    GETHL(g_wq0, wq0h, wq0l)  GETHL(g_wk0, wk0h, wk0l)
    GETHL(g_wv0, wv0h, wv0l)  GETHL(g_wo0, wo0h, wo0l)
    GETHL(g_wq1, wq1h, wq1l)  GETHL(g_wk1, wk1h, wk1l)
    GETHL(g_wv1, wv1h, wv1l)  GETHL(g_wo1, wo1h, wo1l)
    GETHL(g_qb,  qh,   ql)    GETHL(g_kb,  kh,   kl)
    GETHL(g_vt,  vth,  vtl)   GETHL(g_p,   pph,  ppl)
    GETHL(g_attb, atth, attl)

    const int HD  = Hc * DHc;     // 2048
    const int KVD = HKVc * DHc;   // 1024

    // --- split inputs & weights ---
    run_cvt(pg, pgh, pgl, (long)Bc * L1c * DPGc);
    run_cvt(ex, exh, exl, (long)Bc * L2c * DEXc);
    run_cvt(W[0], wq0h, wq0l, (long)HD * DPGc);
    run_cvt(W[1], wk0h, wk0l, (long)KVD * DPGc);
    run_cvt(W[2], wv0h, wv0l, (long)KVD * DPGc);
    run_cvt(W[3], wo0h, wo0l, (long)DPGc * HD);
    run_cvt(W[4], wq1h, wq1l, (long)HD * DEXc);
    run_cvt(W[5], wk1h, wk1l, (long)KVD * DEXc);
    run_cvt(W[6], wv1h, wv1l, (long)KVD * DEXc);
    run_cvt(W[7], wo1h, wo1l, (long)DEXc * HD);

    // --- QKV projections (fp32 out) ---
    run_gemm_tc(pgh, pgl, wq0h, wq0l, q, nullptr, L1c, HD, DPGc,
                DPGc, DPGc, HD, 0,
                (long)L1c * DPGc, 0, 0, 0, (long)Lc * HD, 0, 0, Bc, 1, 1, 1.0f);
    run_gemm_tc(pgh, pgl, wk0h, wk0l, k, nullptr, L1c, KVD, DPGc,
                DPGc, DPGc, KVD, 0,
                (long)L1c * DPGc, 0, 0, 0, (long)Lc * KVD, 0, 0, Bc, 1, 1, 1.0f);
    run_gemm_tc(pgh, pgl, wv0h, wv0l, v, nullptr, L1c, KVD, DPGc,
                DPGc, DPGc, KVD, 0,
                (long)L1c * DPGc, 0, 0, 0, (long)Lc * KVD, 0, 0, Bc, 1, 1, 1.0f);
    run_gemm_tc(exh, exl, wq1h, wq1l, q + (long)L1c * HD, nullptr, L2c, HD, DEXc,
                DEXc, DEXc, HD, 0,
                (long)L2c * DEXc, 0, 0, 0, (long)Lc * HD, 0, 0, Bc, 1, 1, 1.0f);
    run_gemm_tc(exh, exl, wk1h, wk1l, k + (long)L1c * KVD, nullptr, L2c, KVD, DEXc,
                DEXc, DEXc, KVD, 0,
                (long)L2c * DEXc, 0, 0, 0, (long)Lc * KVD, 0, 0, Bc, 1, 1, 1.0f);
    run_gemm_tc(exh, exl, wv1h, wv1l, v + (long)L1c * KVD, nullptr, L2c, KVD, DEXc,
                DEXc, DEXc, KVD, 0,
                (long)L2c * DEXc, 0, 0, 0, (long)Lc * KVD, 0, 0, Bc, 1, 1, 1.0f);

    // --- RoPE + split q, k ---
    {
        long tpq = (long)Bc * Lc * Hc * 128;
        long tpk = (long)Bc * Lc * HKVc * 128;
        rope_cvt_kernel<<<(int)((tpq + 255) / 256), 256>>>(q, cosp, sinp, qh, ql, Hc, tpq);
        rope_cvt_kernel<<<(int)((tpk + 255) / 256), 256>>>(k, cosp, sinp, kh, kl, HKVc, tpk);
    }

    // --- V transpose + split ---
    {
        dim3 g(DHc / 32, Lc / 32, Bc * HKVc);
        vtrans_cvt_kernel<<<g, dim3(32, 8)>>>(v, vth, vtl);
    }

    // --- scores = q @ k^T * SCALE + mask  [B*H batches, GQA rep=2] ---
    run_gemm_tc(qh, ql, kh, kl, sc, mask, Lc, Lc, DHc,
                HD, KVD, Lc, Lc,
                (long)Lc * HD, DHc,
                (long)Lc * KVD, DHc,
                (long)Hc * Lc * Lc, (long)Lc * Lc,
                (long)Lc * Lc,
                Bc * Hc, Hc, 2, SCALEc);

    // --- softmax + split ---
    softmax_cvt_kernel<<<Bc * Hc * Lc, 256>>>(sc, pph, ppl, Lc);

    // --- att = P @ V^T  (NT vs transposed V) ---
    run_gemm_tc(pph, ppl, vth, vtl, att, nullptr, Lc, DHc, Lc,
                Lc, Lc, HD, 0,
                (long)Hc * Lc * Lc, (long)Lc * Lc,
                (long)HKVc * DHc * Lc, (long)DHc * Lc,
                (long)Lc * HD, DHc,
                0, Bc * Hc, Hc, 2, 1.0f);

    // --- split att ---
    run_cvt(att, atth, attl, (long)Bc * Lc * HD);

    // --- output projections ---
    run_gemm_tc(atth, attl, wo0h, wo0l, out, nullptr, L1c, DPGc, HD,
                HD, HD, DPGc, 0,
                (long)Lc * HD, 0, 0, 0,
                (long)L1c * DPGc, 0, 0, Bc, 1, 1, 1.0f);
    run_gemm_tc(atth + (long)L1c * HD, attl + (long)L1c * HD, wo1h, wo1l,
                out + (long)Bc * L1c * DPGc, nullptr, L2c, DEXc, HD,
                HD, HD, DEXc, 0,
                (long)Lc * HD, 0, 0, 0,
                (long)L2c * DEXc, 0, 0, Bc, 1, 1, 1.0f);
}